// round 4
// baseline (speedup 1.0000x reference)
#include <cuda_runtime.h>

// Residual VQ: x [N,128] fp32, codebooks [S,256,128] fp32.
// Output layout (float32): x_q [N*128], mean_loss [1], indices [N*S] (as floats).
//
// One CTA (1024 thr, 32 warps) processes 128 rows through all S stages:
//   stage: load codebook (swizzled, transposed) into SMEM -> GEMM dots (packed
//   fma.rn.f32x2, 2 codes per accumulator, 4 rows/warp) -> argmin ->
//   fp64 rescue for near-ties -> residual update + loss accum.
// x_q = x - final_residual. Loss = 2/(S*N*D) * sum(r_new^2), reduced by the
// last CTA (ticket pattern, fixed-order sum -> deterministic).

#define D        128
#define C        256
#define ROWS     128
#define THREADS  1024
#define NWARP    (THREADS/32)
#define MAXGRID  4096
#define EPS_GAP  1e-2f

__device__ float        g_part[MAXGRID];
__device__ unsigned int g_cnt = 0;

// dynamic smem layout (floats):
//   sR[ROWS*D] | cbT[D*C] | cnormP[4*C] | sIdx[ROWS] (int) | sIdxAll[ROWS*8] |
//   sRed[NWARP] | sCnt[1] (int) | sList[ROWS] (int)
#define SMEM_FLOATS (ROWS*D + D*C + 4*C + ROWS + ROWS*8 + NWARP + 1 + ROWS)

#define FMA2(d, a, b) \
    asm("fma.rn.f32x2 %0, %1, %2, %3;" : "=l"(d) : "l"(a), "l"(b), "l"(d))

__global__ void __launch_bounds__(THREADS, 1)
rvq_kernel(const float* __restrict__ x, const float* __restrict__ cbs,
           float* __restrict__ out, int N, int S)
{
    extern __shared__ float sm[];
    float* sR      = sm;                         // ROWS*D
    float* cbT     = sR + ROWS * D;              // D*C, element (k,c) at [k*C + (c ^ ((k&31)<<2))]
    float* cnormP  = cbT + D * C;                // 4*C partial code norms
    int*   sIdx    = (int*)(cnormP + 4 * C);     // ROWS
    float* sIdxAll = (float*)(sIdx + ROWS);      // ROWS*8
    float* sRed    = sIdxAll + ROWS * 8;         // NWARP
    int*   sCnt    = (int*)(sRed + NWARP);       // 1
    int*   sList   = sCnt + 1;                   // ROWS
    __shared__ int sLast;

    const int tid  = threadIdx.x;
    const int lane = tid & 31;
    const int w    = tid >> 5;                   // warp id 0..31
    const long long rowBase = (long long)blockIdx.x * ROWS;

    // ---- load x tile into sR (coalesced float4) ----
    const float4* xg  = (const float4*)(x + rowBase * D);
    float4*       sR4 = (float4*)sR;
    #pragma unroll
    for (int it = 0; it < (ROWS * D / 4) / THREADS; ++it)
        sR4[tid + it * THREADS] = xg[tid + it * THREADS];

    float lsum = 0.f;

    const int ty     = w;            // base row; warp rows = ty + 32*i
    const int cbase0 = lane * 4;     // code quad base (codes 0..127); quad1 = +128

    for (int s = 0; s < S; ++s) {
        __syncthreads();                 // prev stage done with cbT / sR
        if (tid == 0) *sCnt = 0;
        __syncthreads();

        // ---- load stage codebook -> cbT (swizzled) + partial cnorm ----
        // 4 k-parts per code: part p = w>>3 covers kq in [p*8, p*8+8)
        {
            const float* cb = cbs + (size_t)s * C * D;
            const int code  = ((w & 7) << 5) + lane;     // 0..255
            const int p     = w >> 3;                    // 0..3
            const int kqB   = p * 8;
            float psum = 0.f;
            #pragma unroll
            for (int t = 0; t < 8; ++t) {
                const int kq = kqB + t;
                const float4 v = *(const float4*)(cb + code * D + 4 * kq);
                const int k0 = 4 * kq;
                cbT[(k0 + 0) * C + (code ^ (((k0 + 0) & 31) << 2))] = v.x;
                cbT[(k0 + 1) * C + (code ^ (((k0 + 1) & 31) << 2))] = v.y;
                cbT[(k0 + 2) * C + (code ^ (((k0 + 2) & 31) << 2))] = v.z;
                cbT[(k0 + 3) * C + (code ^ (((k0 + 3) & 31) << 2))] = v.w;
                psum += v.x * v.x + v.y * v.y + v.z * v.z + v.w * v.w;
            }
            cnormP[p * C + code] = psum;   // no atomics; summed in fixed order later
        }
        __syncthreads();

        // ---- GEMM: packed f32x2, acc2[i][p] = dots for code pair p of row ty+32i ----
        // pair map: [0]=(cbase0,+1) [1]=(cbase0+2,+3) [2]=(128+cbase0,+1) [3]=(128+cbase0+2,+3)
        unsigned long long acc2[4][4];
        #pragma unroll
        for (int i = 0; i < 4; ++i)
            #pragma unroll
            for (int p = 0; p < 4; ++p) acc2[i][p] = 0ULL;

        for (int k0 = 0; k0 < D; k0 += 4) {
            float4 rv[4];
            #pragma unroll
            for (int i = 0; i < 4; ++i)
                rv[i] = *(const float4*)&sR[(ty + 32 * i) * D + k0];   // broadcast
            #pragma unroll
            for (int m = 0; m < 4; ++m) {
                const int k  = k0 + m;
                const int sw = (k & 31) << 2;
                const ulonglong2 c0 = *(const ulonglong2*)&cbT[k * C + (cbase0 ^ sw)];
                const ulonglong2 c1 = *(const ulonglong2*)&cbT[k * C + 128 + (cbase0 ^ sw)];
                #pragma unroll
                for (int i = 0; i < 4; ++i) {
                    const float r = (m == 0) ? rv[i].x : (m == 1) ? rv[i].y
                                  : (m == 2) ? rv[i].z : rv[i].w;
                    unsigned long long rr;
                    asm("mov.b64 %0, {%1, %1};" : "=l"(rr) : "f"(r));
                    FMA2(acc2[i][0], rr, c0.x);
                    FMA2(acc2[i][1], rr, c0.y);
                    FMA2(acc2[i][2], rr, c1.x);
                    FMA2(acc2[i][3], rr, c1.y);
                }
            }
        }

        // ---- code norms: fixed-order sum of 4 partials (deterministic) ----
        float4 cn0, cn1;
        {
            const float4* p0 = (const float4*)&cnormP[0 * C];
            const float4* p1 = (const float4*)&cnormP[1 * C];
            const float4* p2 = (const float4*)&cnormP[2 * C];
            const float4* p3 = (const float4*)&cnormP[3 * C];
            const int q0 = cbase0 >> 2, q1 = (128 + cbase0) >> 2;
            float4 a0 = p0[q0], a1 = p1[q0], a2 = p2[q0], a3 = p3[q0];
            cn0.x = ((a0.x + a1.x) + a2.x) + a3.x;
            cn0.y = ((a0.y + a1.y) + a2.y) + a3.y;
            cn0.z = ((a0.z + a1.z) + a2.z) + a3.z;
            cn0.w = ((a0.w + a1.w) + a2.w) + a3.w;
            a0 = p0[q1]; a1 = p1[q1]; a2 = p2[q1]; a3 = p3[q1];
            cn1.x = ((a0.x + a1.x) + a2.x) + a3.x;
            cn1.y = ((a0.y + a1.y) + a2.y) + a3.y;
            cn1.z = ((a0.z + a1.z) + a2.z) + a3.z;
            cn1.w = ((a0.w + a1.w) + a2.w) + a3.w;
        }

        // ---- argmin + second-best over 256 codes per row ----
        #pragma unroll
        for (int i = 0; i < 4; ++i) {
            float d0, d1, sc[8];
            asm("mov.b64 {%0, %1}, %2;" : "=f"(d0), "=f"(d1) : "l"(acc2[i][0]));
            sc[0] = cn0.x - 2.f * d0;  sc[1] = cn0.y - 2.f * d1;
            asm("mov.b64 {%0, %1}, %2;" : "=f"(d0), "=f"(d1) : "l"(acc2[i][1]));
            sc[2] = cn0.z - 2.f * d0;  sc[3] = cn0.w - 2.f * d1;
            asm("mov.b64 {%0, %1}, %2;" : "=f"(d0), "=f"(d1) : "l"(acc2[i][2]));
            sc[4] = cn1.x - 2.f * d0;  sc[5] = cn1.y - 2.f * d1;
            asm("mov.b64 {%0, %1}, %2;" : "=f"(d0), "=f"(d1) : "l"(acc2[i][3]));
            sc[6] = cn1.z - 2.f * d0;  sc[7] = cn1.w - 2.f * d1;

            float b1 = sc[0], b2 = 3.4e38f;
            int   bi = cbase0;
            #pragma unroll
            for (int j = 1; j < 8; ++j) {
                const int idx = (j < 4) ? (cbase0 + j) : (128 + cbase0 + (j - 4));
                if (sc[j] < b1)      { b2 = b1; b1 = sc[j]; bi = idx; }
                else if (sc[j] < b2) { b2 = sc[j]; }
            }
            #pragma unroll
            for (int off = 16; off; off >>= 1) {
                const float ov1 = __shfl_down_sync(0xffffffffu, b1, off);
                const int   oi  = __shfl_down_sync(0xffffffffu, bi, off);
                const float ov2 = __shfl_down_sync(0xffffffffu, b2, off);
                const float m2  = fminf(fmaxf(b1, ov1), fminf(b2, ov2));
                if (ov1 < b1 || (ov1 == b1 && oi < bi)) { b1 = ov1; bi = oi; }
                b2 = m2;
            }
            if (lane == 0) {
                const int row = ty + 32 * i;
                sIdx[row] = bi;
                sIdxAll[row * 8 + s] = (float)bi;
                if (b2 - b1 < EPS_GAP) {
                    const int pos = atomicAdd(sCnt, 1);
                    sList[pos] = row;
                }
            }
        }
        __syncthreads();

        // ---- fp64 rescue for near-tie rows (rare) ----
        {
            const int cnt = *sCnt;
            for (int e = w; e < cnt; e += NWARP) {
                const int row = sList[e];
                const float* rrow = &sR[row * D];
                double bestd = 1e300;
                int bestidx = 0;
                for (int j = lane; j < C; j += 32) {   // ascending j per lane
                    double dsum = 0.0;
                    for (int k = 0; k < D; ++k) {
                        const float cv = cbT[k * C + (j ^ ((k & 31) << 2))];
                        const double diff = (double)rrow[k] - (double)cv;
                        dsum = fma(diff, diff, dsum);
                    }
                    if (dsum < bestd) { bestd = dsum; bestidx = j; }
                }
                #pragma unroll
                for (int off = 16; off; off >>= 1) {
                    const double ov = __shfl_down_sync(0xffffffffu, bestd, off);
                    const int    oi = __shfl_down_sync(0xffffffffu, bestidx, off);
                    if (ov < bestd || (ov == bestd && oi < bestidx)) { bestd = ov; bestidx = oi; }
                }
                if (lane == 0) {
                    sIdx[row] = bestidx;
                    sIdxAll[row * 8 + s] = (float)bestidx;
                }
            }
        }
        __syncthreads();

        // ---- residual update + loss ----
        #pragma unroll
        for (int it = 0; it < (ROWS * D) / THREADS; ++it) {
            const int e   = tid + it * THREADS;
            const int row = e >> 7, k = e & 127;
            const int idx = sIdx[row];
            const float cv = cbT[k * C + (idx ^ ((k & 31) << 2))];
            const float r  = sR[e] - cv;
            sR[e] = r;
            lsum += r * r;
        }
    }
    __syncthreads();

    // ---- x_q = x - final residual ----
    float4* og = (float4*)(out + rowBase * D);
    #pragma unroll
    for (int it = 0; it < (ROWS * D / 4) / THREADS; ++it) {
        const float4 xv = xg[tid + it * THREADS];
        const float4 rv = sR4[tid + it * THREADS];
        float4 o;
        o.x = xv.x - rv.x; o.y = xv.y - rv.y; o.z = xv.z - rv.z; o.w = xv.w - rv.w;
        og[tid + it * THREADS] = o;
    }

    // ---- indices (float) ----
    float* oIdx = out + (size_t)N * D + 1;
    for (int e = tid; e < ROWS * S; e += THREADS) {
        const int row = e / S, st = e % S;
        oIdx[(rowBase + row) * S + st] = sIdxAll[row * 8 + st];
    }

    // ---- per-CTA loss partial ----
    #pragma unroll
    for (int off = 16; off; off >>= 1)
        lsum += __shfl_down_sync(0xffffffffu, lsum, off);
    if (lane == 0) sRed[w] = lsum;
    __syncthreads();
    if (tid == 0) {
        float t = 0.f;
        #pragma unroll
        for (int i = 0; i < NWARP; ++i) t += sRed[i];
        g_part[blockIdx.x] = t;
        __threadfence();
        const unsigned int ticket = atomicAdd(&g_cnt, 1u);
        sLast = (ticket == (unsigned int)gridDim.x - 1u) ? 1 : 0;
    }
    __syncthreads();

    // ---- last CTA: deterministic fixed-order loss reduction ----
    if (sLast) {
        __threadfence();
        const int nPart = gridDim.x;
        float ssum = 0.f;
        for (int i = tid; i < nPart; i += THREADS) ssum += g_part[i];
        #pragma unroll
        for (int off = 16; off; off >>= 1)
            ssum += __shfl_down_sync(0xffffffffu, ssum, off);
        if (lane == 0) sRed[w] = ssum;
        __syncthreads();
        if (tid == 0) {
            float t = 0.f;
            #pragma unroll
            for (int i = 0; i < NWARP; ++i) t += sRed[i];
            const float scale = 2.f / ((float)S * (float)N * (float)D);
            out[(size_t)N * D] = t * scale;
            g_cnt = 0;                       // reset for next graph replay
        }
    }
}

extern "C" void kernel_launch(void* const* d_in, const int* in_sizes, int n_in,
                              void* d_out, int out_size)
{
    const float* x   = (const float*)d_in[0];
    const float* cbs = (const float*)d_in[1];
    float* out = (float*)d_out;

    const int N = in_sizes[0] / D;              // 262144
    const int S = in_sizes[1] / (C * D);        // 4
    const int nBlocks = N / ROWS;               // 2048

    const size_t smemBytes = SMEM_FLOATS * sizeof(float);
    cudaFuncSetAttribute(rvq_kernel, cudaFuncAttributeMaxDynamicSharedMemorySize,
                         (int)smemBytes);

    rvq_kernel<<<nBlocks, THREADS, smemBytes>>>(x, cbs, out, N, S);
}

// round 6
// speedup vs baseline: 1.0950x; 1.0950x over previous
#include <cuda_runtime.h>

// Residual VQ via portable tf32 tensor-core MMA (mma.sync.m16n8k8).
// x [N,128] fp32, codebooks [S,256,128] fp32.
// Output (float32): x_q [N*128], mean_loss [1], indices [N*S].
//
// One CTA (512 thr, 16 warps) owns 128 rows across all S stages:
//   stage: codebook -> SMEM B [256][132] + cnorm; tf32 MMA scores D[128,256];
//   per-row tf32 top-2; gap<EPS1 -> exact fp32 full rescan (warp/row);
//   fp32 gap<EPS2 -> fp64 full rescan; residual update in SMEM A [128][132].
// x_q = x - final residual. Loss = 2/(S*N*D)*sum(r_new^2), last-CTA reduce.

#define D        128
#define C        256
#define ROWS     128
#define THREADS  512
#define NWARP    16
#define MAXGRID  4096
#define EPS1     0.5f
#define EPS2     1e-2f
#define LDA      132            // padded row stride (floats)

__device__ float        g_part[MAXGRID];
__device__ unsigned int g_cnt = 0;

// dynamic smem (floats):
//  A[128*132] | B[256*132] | cnorm[256] | pB1[512] | pB2[512] | pI1[512](int) |
//  sIdx[128](int) | sIdxAll[128*8] | sRed[32] | sCnt(int) | sList[128](int)
#define OFF_A    0
#define OFF_B    (OFF_A + ROWS*LDA)
#define OFF_CN   (OFF_B + C*LDA)
#define OFF_PB1  (OFF_CN + 256)
#define OFF_PB2  (OFF_PB1 + 512)
#define OFF_PI1  (OFF_PB2 + 512)
#define OFF_IDX  (OFF_PI1 + 512)
#define OFF_IALL (OFF_IDX + 128)
#define OFF_RED  (OFF_IALL + 128*8)
#define OFF_CNT  (OFF_RED + 32)
#define OFF_LIST (OFF_CNT + 1)
#define SMEM_FLOATS (OFF_LIST + 128)
#define SMEM_BYTES  (SMEM_FLOATS * 4 + 64)

#define MMA_TF32(c0,c1,c2,c3,a0,a1,a2,a3,b0,b1) \
    asm volatile("mma.sync.aligned.m16n8k8.row.col.f32.tf32.tf32.f32 " \
                 "{%0,%1,%2,%3},{%4,%5,%6,%7},{%8,%9},{%0,%1,%2,%3};" \
                 : "+f"(c0), "+f"(c1), "+f"(c2), "+f"(c3) \
                 : "r"(a0), "r"(a1), "r"(a2), "r"(a3), "r"(b0), "r"(b1))

__global__ void __launch_bounds__(THREADS, 1)
rvq_kernel(const float* __restrict__ x, const float* __restrict__ cbs,
           float* __restrict__ out, int N, int S)
{
    extern __shared__ float sm[];
    float* A       = sm + OFF_A;            // residual [row][k], stride 132
    float* B       = sm + OFF_B;            // codebook [code][k], stride 132
    float* cnorm   = sm + OFF_CN;
    float* pB1     = sm + OFF_PB1;          // partial best  [row*4 + ct]
    float* pB2     = sm + OFF_PB2;          // partial 2nd   [row*4 + ct]
    int*   pI1     = (int*)(sm + OFF_PI1);  // partial index [row*4 + ct]
    int*   sIdx    = (int*)(sm + OFF_IDX);
    float* sIdxAll = sm + OFF_IALL;
    float* sRed    = sm + OFF_RED;
    int*   sCnt    = (int*)(sm + OFF_CNT);
    int*   sList   = (int*)(sm + OFF_LIST);
    __shared__ int sLast;

    const int tid  = threadIdx.x;
    const int lane = tid & 31;
    const int w    = tid >> 5;
    const int g    = lane >> 2;      // mma group id (0..7)
    const int t    = lane & 3;       // mma thread-in-group (0..3)
    const long long rowBase = (long long)blockIdx.x * ROWS;

    // ---- load x tile into A ----
    {
        const int r4 = lane >> 3, f = lane & 7;
        #pragma unroll
        for (int h = 0; h < 2; ++h) {
            const int row = 8 * w + 4 * h + r4;
            #pragma unroll
            for (int j = 0; j < 4; ++j) {
                const int k = j * 32 + f * 4;
                *(float4*)(A + row * LDA + k) =
                    *(const float4*)(x + (rowBase + row) * D + k);
            }
        }
    }

    float lsum = 0.f;
    const int rt   = w & 7;          // row tile (16 rows)
    const int ctp  = (w >> 3) * 2;   // first code tile (64 codes) of this warp
    const int arow = rt * 16 + g;

    for (int s = 0; s < S; ++s) {
        __syncthreads();             // previous stage done with B
        if (tid == 0) *sCnt = 0;

        // ---- codebook stage s -> B + cnorm (fixed-tree reduce) ----
        {
            const float* cb = cbs + (size_t)s * C * D;
            const int r4 = lane >> 3, f = lane & 7;
            #pragma unroll
            for (int i = 0; i < 4; ++i) {
                const int code = 16 * w + 4 * i + r4;
                float psum = 0.f;
                #pragma unroll
                for (int j = 0; j < 4; ++j) {
                    const int k = j * 32 + f * 4;
                    const float4 v = *(const float4*)(cb + code * D + k);
                    *(float4*)(B + code * LDA + k) = v;
                    psum += v.x * v.x + v.y * v.y + v.z * v.z + v.w * v.w;
                }
                psum += __shfl_down_sync(0xffffffffu, psum, 4);
                psum += __shfl_down_sync(0xffffffffu, psum, 2);
                psum += __shfl_down_sync(0xffffffffu, psum, 1);
                if (f == 0) cnorm[code] = psum;
            }
        }
        __syncthreads();

        // ---- tf32 MMA: dots[16 rows][128 codes] per warp ----
        float acc[2][8][4];
        #pragma unroll
        for (int c = 0; c < 2; ++c)
            #pragma unroll
            for (int n = 0; n < 8; ++n)
                #pragma unroll
                for (int q = 0; q < 4; ++q) acc[c][n][q] = 0.f;

        const unsigned* Au = (const unsigned*)A;
        const unsigned* Bu = (const unsigned*)B;
        #pragma unroll
        for (int kt = 0; kt < 16; ++kt) {
            const int kb = kt * 8;
            const unsigned a0 = Au[ arow      * LDA + kb + t];
            const unsigned a1 = Au[(arow + 8) * LDA + kb + t];
            const unsigned a2 = Au[ arow      * LDA + kb + t + 4];
            const unsigned a3 = Au[(arow + 8) * LDA + kb + t + 4];
            #pragma unroll
            for (int c = 0; c < 2; ++c) {
                const int n0 = (ctp + c) * 64;
                #pragma unroll
                for (int n = 0; n < 8; ++n) {
                    const int code = n0 + n * 8 + g;
                    const unsigned b0 = Bu[code * LDA + kb + t];
                    const unsigned b1 = Bu[code * LDA + kb + t + 4];
                    MMA_TF32(acc[c][n][0], acc[c][n][1], acc[c][n][2], acc[c][n][3],
                             a0, a1, a2, a3, b0, b1);
                }
            }
        }

        // ---- per-(row, code-tile) top-2 partials ----
        #pragma unroll
        for (int c = 0; c < 2; ++c) {
            const int ct = ctp + c;
            #pragma unroll
            for (int h = 0; h < 2; ++h) {           // h=0: row=arow, h=1: arow+8
                float b1v = 3.4e38f, b2v = 3.4e38f;
                int   i1  = 0;
                #pragma unroll
                for (int n = 0; n < 8; ++n) {
                    const int code0 = ct * 64 + n * 8 + 2 * t;
                    const float s0 = fmaf(-2.f, acc[c][n][h * 2 + 0], cnorm[code0]);
                    const float s1 = fmaf(-2.f, acc[c][n][h * 2 + 1], cnorm[code0 + 1]);
                    if (s0 < b1v) { b2v = b1v; b1v = s0; i1 = code0; }
                    else if (s0 < b2v) b2v = s0;
                    if (s1 < b1v) { b2v = b1v; b1v = s1; i1 = code0 + 1; }
                    else if (s1 < b2v) b2v = s1;
                }
                #pragma unroll
                for (int off = 1; off <= 2; off <<= 1) {
                    const float ov1 = __shfl_xor_sync(0xffffffffu, b1v, off);
                    const int   oi  = __shfl_xor_sync(0xffffffffu, i1, off);
                    const float ov2 = __shfl_xor_sync(0xffffffffu, b2v, off);
                    const float m2  = fminf(fmaxf(b1v, ov1), fminf(b2v, ov2));
                    if (ov1 < b1v || (ov1 == b1v && oi < i1)) { b1v = ov1; i1 = oi; }
                    b2v = m2;
                }
                if (t == 0) {
                    const int row = arow + 8 * h;
                    pB1[row * 4 + ct] = b1v;
                    pB2[row * 4 + ct] = b2v;
                    pI1[row * 4 + ct] = i1;
                }
            }
        }
        __syncthreads();

        // ---- merge 4 code-tile partials per row; nominate rescans ----
        if (w < 4) {
            const int row = w * 32 + lane;
            float b1v = 3.4e38f, b2v = 3.4e38f;
            int   i1  = 0;
            #pragma unroll
            for (int ct = 0; ct < 4; ++ct) {
                const float ov1 = pB1[row * 4 + ct];
                const float ov2 = pB2[row * 4 + ct];
                const int   oi  = pI1[row * 4 + ct];
                const float m2  = fminf(fmaxf(b1v, ov1), fminf(b2v, ov2));
                if (ov1 < b1v || (ov1 == b1v && oi < i1)) { b1v = ov1; i1 = oi; }
                b2v = m2;
            }
            if (b2v - b1v < EPS1) {
                const int pos = atomicAdd(sCnt, 1);
                sList[pos] = row;
            } else {
                sIdx[row] = i1;
                sIdxAll[row * 8 + s] = (float)i1;
            }
        }
        __syncthreads();

        // ---- rescue: exact fp32 full rescan (warp per row); fp64 if still close ----
        {
            const int cnt = *sCnt;
            for (int e = w; e < cnt; e += NWARP) {
                const int row = sList[e];
                const float4* Ar = (const float4*)(A + row * LDA);
                float b1v = 3.4e38f, b2v = 3.4e38f;
                int   i1  = 0x7fffffff;
                #pragma unroll
                for (int cc = 0; cc < 8; ++cc) {
                    const int code = lane * 8 + cc;
                    const float4* Bc = (const float4*)(B + code * LDA);
                    float dot = 0.f;
                    #pragma unroll
                    for (int q = 0; q < 32; ++q) {
                        const float4 rv = Ar[q], cv = Bc[q];
                        dot = fmaf(rv.x, cv.x, dot); dot = fmaf(rv.y, cv.y, dot);
                        dot = fmaf(rv.z, cv.z, dot); dot = fmaf(rv.w, cv.w, dot);
                    }
                    const float sc = fmaf(-2.f, dot, cnorm[code]);
                    if (sc < b1v) { b2v = b1v; b1v = sc; i1 = code; }
                    else if (sc < b2v) b2v = sc;
                }
                #pragma unroll
                for (int off = 16; off; off >>= 1) {
                    const float ov1 = __shfl_xor_sync(0xffffffffu, b1v, off);
                    const int   oi  = __shfl_xor_sync(0xffffffffu, i1, off);
                    const float ov2 = __shfl_xor_sync(0xffffffffu, b2v, off);
                    const float m2  = fminf(fmaxf(b1v, ov1), fminf(b2v, ov2));
                    if (ov1 < b1v || (ov1 == b1v && oi < i1)) { b1v = ov1; i1 = oi; }
                    b2v = m2;
                }
                int best = i1;
                if (b2v - b1v < EPS2) {
                    // fp64 full rescan, first-index tie-break
                    double d1 = 1e300; int di = 0x7fffffff;
                    #pragma unroll
                    for (int cc = 0; cc < 8; ++cc) {
                        const int code = lane * 8 + cc;
                        const float* Bc = B + code * LDA;
                        const float* Arf = A + row * LDA;
                        double dsum = 0.0;
                        for (int k = 0; k < D; ++k) {
                            const double df = (double)Arf[k] - (double)Bc[k];
                            dsum = fma(df, df, dsum);
                        }
                        if (dsum < d1) { d1 = dsum; di = code; }
                    }
                    #pragma unroll
                    for (int off = 16; off; off >>= 1) {
                        const double ov = __shfl_xor_sync(0xffffffffu, d1, off);
                        const int    oi = __shfl_xor_sync(0xffffffffu, di, off);
                        if (ov < d1 || (ov == d1 && oi < di)) { d1 = ov; di = oi; }
                    }
                    best = di;
                }
                if (lane == 0) {
                    sIdx[row] = best;
                    sIdxAll[row * 8 + s] = (float)best;
                }
            }
        }
        __syncthreads();

        // ---- residual update + loss ----
        {
            const int r4 = lane >> 3, f = lane & 7;
            #pragma unroll
            for (int h = 0; h < 2; ++h) {
                const int row = 8 * w + 4 * h + r4;
                const int idx = sIdx[row];
                #pragma unroll
                for (int j = 0; j < 4; ++j) {
                    const int k = j * 32 + f * 4;
                    float4 rv = *(const float4*)(A + row * LDA + k);
                    const float4 cv = *(const float4*)(B + idx * LDA + k);
                    rv.x -= cv.x; rv.y -= cv.y; rv.z -= cv.z; rv.w -= cv.w;
                    *(float4*)(A + row * LDA + k) = rv;
                    lsum += rv.x * rv.x + rv.y * rv.y + rv.z * rv.z + rv.w * rv.w;
                }
            }
        }
    }
    __syncthreads();

    // ---- x_q = x - final residual ----
    {
        const int r4 = lane >> 3, f = lane & 7;
        #pragma unroll
        for (int h = 0; h < 2; ++h) {
            const int row = 8 * w + 4 * h + r4;
            #pragma unroll
            for (int j = 0; j < 4; ++j) {
                const int k = j * 32 + f * 4;
                const float4 xv = *(const float4*)(x + (rowBase + row) * D + k);
                const float4 rv = *(const float4*)(A + row * LDA + k);
                float4 o;
                o.x = xv.x - rv.x; o.y = xv.y - rv.y;
                o.z = xv.z - rv.z; o.w = xv.w - rv.w;
                *(float4*)(out + (rowBase + row) * D + k) = o;
            }
        }
    }

    // ---- indices (float) ----
    float* oIdx = out + (size_t)N * D + 1;
    for (int e = tid; e < ROWS * S; e += THREADS) {
        const int row = e / S, st = e % S;
        oIdx[(rowBase + row) * S + st] = sIdxAll[row * 8 + st];
    }

    // ---- per-CTA loss partial + last-CTA deterministic reduce ----
    #pragma unroll
    for (int off = 16; off; off >>= 1)
        lsum += __shfl_down_sync(0xffffffffu, lsum, off);
    if (lane == 0) sRed[w] = lsum;
    __syncthreads();
    if (tid == 0) {
        float tt = 0.f;
        #pragma unroll
        for (int i = 0; i < NWARP; ++i) tt += sRed[i];
        g_part[blockIdx.x] = tt;
        __threadfence();
        const unsigned ticket = atomicAdd(&g_cnt, 1u);
        sLast = (ticket == (unsigned)gridDim.x - 1u) ? 1 : 0;
    }
    __syncthreads();

    if (sLast) {
        __threadfence();
        const int nPart = gridDim.x;
        float ssum = 0.f;
        for (int i = tid; i < nPart; i += THREADS) ssum += g_part[i];
        #pragma unroll
        for (int off = 16; off; off >>= 1)
            ssum += __shfl_down_sync(0xffffffffu, ssum, off);
        if (lane == 0) sRed[w] = ssum;
        __syncthreads();
        if (tid == 0) {
            float tt = 0.f;
            #pragma unroll
            for (int i = 0; i < NWARP; ++i) tt += sRed[i];
            const float scale = 2.f / ((float)S * (float)N * (float)D);
            out[(size_t)N * D] = tt * scale;
            g_cnt = 0;                   // reset for next graph replay
        }
    }
}

extern "C" void kernel_launch(void* const* d_in, const int* in_sizes, int n_in,
                              void* d_out, int out_size)
{
    const float* x   = (const float*)d_in[0];
    const float* cbs = (const float*)d_in[1];
    float* out = (float*)d_out;

    const int N = in_sizes[0] / D;              // 262144
    const int S = in_sizes[1] / (C * D);        // 4
    const int nBlocks = N / ROWS;               // 2048

    cudaFuncSetAttribute(rvq_kernel, cudaFuncAttributeMaxDynamicSharedMemorySize,
                         SMEM_BYTES);
    rvq_kernel<<<nBlocks, THREADS, SMEM_BYTES>>>(x, cbs, out, N, S);
}

// round 7
// speedup vs baseline: 1.2577x; 1.1486x over previous
#include <cuda_runtime.h>

// Residual VQ via portable tf32 tensor-core MMA (mma.sync.m16n8k8).
// x [N,128] fp32, codebooks [S,256,128] fp32.
// Output (float32): x_q [N*128], mean_loss [1], indices [N*S].
//
// One CTA (1024 thr, 32 warps) owns 128 rows across all S stages.
// Warp tile: 32 rows x 32 codes (rt = w&3, ct = w>>2).
//   stage: codebook -> SMEM B [256][132] + cnorm; tf32 MMA scores;
//   per-row tf32 top-2 (8 partials/row); gap<EPS1 -> exact fp32 full rescan;
//   fp32 gap<EPS2 -> fp64 full rescan; residual update in SMEM A [128][132].
// x_q = x - final residual. Loss = 2/(S*N*D)*sum(r_new^2), last-CTA reduce.

#define D        128
#define C        256
#define ROWS     128
#define THREADS  1024
#define NWARP    32
#define MAXGRID  4096
#define EPS1     0.5f
#define EPS2     1e-2f
#define LDA      132            // padded row stride (floats)

__device__ float        g_part[MAXGRID];
__device__ unsigned int g_cnt = 0;

// dynamic smem (floats)
#define OFF_A    0
#define OFF_B    (OFF_A + ROWS*LDA)
#define OFF_CN   (OFF_B + C*LDA)
#define OFF_PB1  (OFF_CN + 256)
#define OFF_PB2  (OFF_PB1 + 1024)
#define OFF_PI1  (OFF_PB2 + 1024)
#define OFF_IDX  (OFF_PI1 + 1024)
#define OFF_IALL (OFF_IDX + 128)
#define OFF_RED  (OFF_IALL + 128*8)
#define OFF_CNT  (OFF_RED + 32)
#define OFF_LIST (OFF_CNT + 1)
#define SMEM_FLOATS (OFF_LIST + 128)
#define SMEM_BYTES  (SMEM_FLOATS * 4 + 64)

#define MMA_TF32(c0,c1,c2,c3,a0,a1,a2,a3,b0,b1) \
    asm volatile("mma.sync.aligned.m16n8k8.row.col.f32.tf32.tf32.f32 " \
                 "{%0,%1,%2,%3},{%4,%5,%6,%7},{%8,%9},{%0,%1,%2,%3};" \
                 : "+f"(c0), "+f"(c1), "+f"(c2), "+f"(c3) \
                 : "r"(a0), "r"(a1), "r"(a2), "r"(a3), "r"(b0), "r"(b1))

__global__ void __launch_bounds__(THREADS, 1)
rvq_kernel(const float* __restrict__ x, const float* __restrict__ cbs,
           float* __restrict__ out, int N, int S)
{
    extern __shared__ float sm[];
    float* A       = sm + OFF_A;            // residual [row][k], stride 132
    float* B       = sm + OFF_B;            // codebook [code][k], stride 132
    float* cnorm   = sm + OFF_CN;
    float* pB1     = sm + OFF_PB1;          // partial best  [row*8 + ct]
    float* pB2     = sm + OFF_PB2;          // partial 2nd   [row*8 + ct]
    int*   pI1     = (int*)(sm + OFF_PI1);  // partial index [row*8 + ct]
    int*   sIdx    = (int*)(sm + OFF_IDX);
    float* sIdxAll = sm + OFF_IALL;
    float* sRed    = sm + OFF_RED;
    int*   sCnt    = (int*)(sm + OFF_CNT);
    int*   sList   = (int*)(sm + OFF_LIST);
    __shared__ int sLast;

    const int tid  = threadIdx.x;
    const int lane = tid & 31;
    const int w    = tid >> 5;       // 0..31
    const int g    = lane >> 2;      // mma group (0..7)
    const int t    = lane & 3;       // thread-in-group (0..3)
    const long long rowBase = (long long)blockIdx.x * ROWS;

    const int rt = w & 3;            // row tile: rows [rt*32, rt*32+32)
    const int ct = w >> 2;           // code tile: codes [ct*32, ct*32+32)
    const int arow = rt * 32 + g;

    // ---- load x tile into A: warp w -> rows [4w, 4w+4) ----
    {
        const int r8 = lane >> 3, f = lane & 7;
        const int row = 4 * w + r8;
        #pragma unroll
        for (int j = 0; j < 4; ++j) {
            const int k = j * 32 + f * 4;
            *(float4*)(A + row * LDA + k) =
                *(const float4*)(x + (rowBase + row) * D + k);
        }
    }

    float lsum = 0.f;

    for (int s = 0; s < S; ++s) {
        __syncthreads();             // previous stage done with B
        if (tid == 0) *sCnt = 0;

        // ---- codebook stage s -> B + cnorm (fixed-tree reduce over 8 lanes) ----
        {
            const float* cb = cbs + (size_t)s * C * D;
            const int r8 = lane >> 3, f = lane & 7;
            #pragma unroll
            for (int i = 0; i < 2; ++i) {
                const int code = 8 * w + 4 * i + r8;
                float psum = 0.f;
                #pragma unroll
                for (int j = 0; j < 4; ++j) {
                    const int k = j * 32 + f * 4;
                    const float4 v = *(const float4*)(cb + code * D + k);
                    *(float4*)(B + code * LDA + k) = v;
                    psum += v.x * v.x + v.y * v.y + v.z * v.z + v.w * v.w;
                }
                psum += __shfl_down_sync(0xffffffffu, psum, 4);
                psum += __shfl_down_sync(0xffffffffu, psum, 2);
                psum += __shfl_down_sync(0xffffffffu, psum, 1);
                if (f == 0) cnorm[code] = psum;
            }
        }
        __syncthreads();

        // ---- tf32 MMA: dots[32 rows][32 codes] per warp ----
        // acc[h][n][quad]: h = m-tile (rows arow+16h, +8), n = n-tile (8 codes)
        float acc[2][4][4];
        #pragma unroll
        for (int h = 0; h < 2; ++h)
            #pragma unroll
            for (int n = 0; n < 4; ++n)
                #pragma unroll
                for (int q = 0; q < 4; ++q) acc[h][n][q] = 0.f;

        const unsigned* Au = (const unsigned*)A;
        const unsigned* Bu = (const unsigned*)B;
        #pragma unroll 4
        for (int kt = 0; kt < 16; ++kt) {
            const int kb = kt * 8;
            unsigned af[2][4];
            #pragma unroll
            for (int h = 0; h < 2; ++h) {
                const int r0 = arow + 16 * h;
                af[h][0] = Au[ r0      * LDA + kb + t];
                af[h][1] = Au[(r0 + 8) * LDA + kb + t];
                af[h][2] = Au[ r0      * LDA + kb + t + 4];
                af[h][3] = Au[(r0 + 8) * LDA + kb + t + 4];
            }
            unsigned bf[4][2];
            #pragma unroll
            for (int n = 0; n < 4; ++n) {
                const int code = ct * 32 + n * 8 + g;
                bf[n][0] = Bu[code * LDA + kb + t];
                bf[n][1] = Bu[code * LDA + kb + t + 4];
            }
            #pragma unroll
            for (int h = 0; h < 2; ++h)
                #pragma unroll
                for (int n = 0; n < 4; ++n)
                    MMA_TF32(acc[h][n][0], acc[h][n][1], acc[h][n][2], acc[h][n][3],
                             af[h][0], af[h][1], af[h][2], af[h][3],
                             bf[n][0], bf[n][1]);
        }

        // ---- per-(row, code-tile) top-2 partials ----
        #pragma unroll
        for (int h = 0; h < 2; ++h) {
            #pragma unroll
            for (int rr = 0; rr < 2; ++rr) {        // row = arow + 16h + 8rr
                float b1v = 3.4e38f, b2v = 3.4e38f;
                int   i1  = 0;
                #pragma unroll
                for (int n = 0; n < 4; ++n) {
                    const int code0 = ct * 32 + n * 8 + 2 * t;
                    const float s0 = fmaf(-2.f, acc[h][n][rr * 2 + 0], cnorm[code0]);
                    const float s1 = fmaf(-2.f, acc[h][n][rr * 2 + 1], cnorm[code0 + 1]);
                    if (s0 < b1v) { b2v = b1v; b1v = s0; i1 = code0; }
                    else if (s0 < b2v) b2v = s0;
                    if (s1 < b1v) { b2v = b1v; b1v = s1; i1 = code0 + 1; }
                    else if (s1 < b2v) b2v = s1;
                }
                #pragma unroll
                for (int off = 1; off <= 2; off <<= 1) {
                    const float ov1 = __shfl_xor_sync(0xffffffffu, b1v, off);
                    const int   oi  = __shfl_xor_sync(0xffffffffu, i1, off);
                    const float ov2 = __shfl_xor_sync(0xffffffffu, b2v, off);
                    const float m2  = fminf(fmaxf(b1v, ov1), fminf(b2v, ov2));
                    if (ov1 < b1v || (ov1 == b1v && oi < i1)) { b1v = ov1; i1 = oi; }
                    b2v = m2;
                }
                if (t == 0) {
                    const int row = arow + 16 * h + 8 * rr;
                    pB1[row * 8 + ct] = b1v;
                    pB2[row * 8 + ct] = b2v;
                    pI1[row * 8 + ct] = i1;
                }
            }
        }
        __syncthreads();

        // ---- merge 8 code-tile partials per row; nominate rescans ----
        if (w < 4) {
            const int row = w * 32 + lane;
            float b1v = 3.4e38f, b2v = 3.4e38f;
            int   i1  = 0;
            #pragma unroll
            for (int c = 0; c < 8; ++c) {
                const float ov1 = pB1[row * 8 + c];
                const float ov2 = pB2[row * 8 + c];
                const int   oi  = pI1[row * 8 + c];
                const float m2  = fminf(fmaxf(b1v, ov1), fminf(b2v, ov2));
                if (ov1 < b1v || (ov1 == b1v && oi < i1)) { b1v = ov1; i1 = oi; }
                b2v = m2;
            }
            if (b2v - b1v < EPS1) {
                const int pos = atomicAdd(sCnt, 1);
                sList[pos] = row;
            } else {
                sIdx[row] = i1;
                sIdxAll[row * 8 + s] = (float)i1;
            }
        }
        __syncthreads();

        // ---- rescue: exact fp32 full rescan (warp per row), conflict-free ----
        {
            const int cnt = *sCnt;
            for (int e = w; e < cnt; e += NWARP) {
                const int row = sList[e];
                const float4* Ar = (const float4*)(A + row * LDA);
                float b1v = 3.4e38f, b2v = 3.4e38f;
                int   i1  = 0x7fffffff;
                #pragma unroll
                for (int cc = 0; cc < 8; ++cc) {
                    const int code = cc * 32 + lane;      // stride-1 across lanes
                    const float4* Bc = (const float4*)(B + code * LDA);
                    float dot = 0.f;
                    #pragma unroll
                    for (int q = 0; q < 32; ++q) {
                        const float4 rv = Ar[q], cv = Bc[q];
                        dot = fmaf(rv.x, cv.x, dot); dot = fmaf(rv.y, cv.y, dot);
                        dot = fmaf(rv.z, cv.z, dot); dot = fmaf(rv.w, cv.w, dot);
                    }
                    const float sc = fmaf(-2.f, dot, cnorm[code]);
                    if (sc < b1v || (sc == b1v && code < i1)) { b2v = b1v; b1v = sc; i1 = code; }
                    else if (sc < b2v) b2v = sc;
                }
                #pragma unroll
                for (int off = 16; off; off >>= 1) {
                    const float ov1 = __shfl_xor_sync(0xffffffffu, b1v, off);
                    const int   oi  = __shfl_xor_sync(0xffffffffu, i1, off);
                    const float ov2 = __shfl_xor_sync(0xffffffffu, b2v, off);
                    const float m2  = fminf(fmaxf(b1v, ov1), fminf(b2v, ov2));
                    if (ov1 < b1v || (ov1 == b1v && oi < i1)) { b1v = ov1; i1 = oi; }
                    b2v = m2;
                }
                int best = i1;
                if (b2v - b1v < EPS2) {
                    // fp64 full rescan, first-index tie-break
                    double d1 = 1e300; int di = 0x7fffffff;
                    #pragma unroll
                    for (int cc = 0; cc < 8; ++cc) {
                        const int code = cc * 32 + lane;
                        const float* Bc = B + code * LDA;
                        const float* Arf = A + row * LDA;
                        double dsum = 0.0;
                        for (int k = 0; k < D; ++k) {
                            const double df = (double)Arf[k] - (double)Bc[k];
                            dsum = fma(df, df, dsum);
                        }
                        if (dsum < d1 || (dsum == d1 && code < di)) { d1 = dsum; di = code; }
                    }
                    #pragma unroll
                    for (int off = 16; off; off >>= 1) {
                        const double ov = __shfl_xor_sync(0xffffffffu, d1, off);
                        const int    oi = __shfl_xor_sync(0xffffffffu, di, off);
                        if (ov < d1 || (ov == d1 && oi < di)) { d1 = ov; di = oi; }
                    }
                    best = di;
                }
                if (lane == 0) {
                    sIdx[row] = best;
                    sIdxAll[row * 8 + s] = (float)best;
                }
            }
        }
        __syncthreads();

        // ---- residual update + loss: warp w -> rows [4w, 4w+4) ----
        {
            const int r8 = lane >> 3, f = lane & 7;
            const int row = 4 * w + r8;
            const int idx = sIdx[row];
            #pragma unroll
            for (int j = 0; j < 4; ++j) {
                const int k = j * 32 + f * 4;
                float4 rv = *(const float4*)(A + row * LDA + k);
                const float4 cv = *(const float4*)(B + idx * LDA + k);
                rv.x -= cv.x; rv.y -= cv.y; rv.z -= cv.z; rv.w -= cv.w;
                *(float4*)(A + row * LDA + k) = rv;
                lsum += rv.x * rv.x + rv.y * rv.y + rv.z * rv.z + rv.w * rv.w;
            }
        }
    }
    __syncthreads();

    // ---- x_q = x - final residual ----
    {
        const int r8 = lane >> 3, f = lane & 7;
        const int row = 4 * w + r8;
        #pragma unroll
        for (int j = 0; j < 4; ++j) {
            const int k = j * 32 + f * 4;
            const float4 xv = *(const float4*)(x + (rowBase + row) * D + k);
            const float4 rv = *(const float4*)(A + row * LDA + k);
            float4 o;
            o.x = xv.x - rv.x; o.y = xv.y - rv.y;
            o.z = xv.z - rv.z; o.w = xv.w - rv.w;
            *(float4*)(out + (rowBase + row) * D + k) = o;
        }
    }

    // ---- indices (float) ----
    float* oIdx = out + (size_t)N * D + 1;
    for (int e = tid; e < ROWS * S; e += THREADS) {
        const int row = e / S, st = e % S;
        oIdx[(rowBase + row) * S + st] = sIdxAll[row * 8 + st];
    }

    // ---- per-CTA loss partial + last-CTA deterministic reduce ----
    #pragma unroll
    for (int off = 16; off; off >>= 1)
        lsum += __shfl_down_sync(0xffffffffu, lsum, off);
    if (lane == 0) sRed[w] = lsum;
    __syncthreads();
    if (tid == 0) {
        float tt = 0.f;
        #pragma unroll
        for (int i = 0; i < NWARP; ++i) tt += sRed[i];
        g_part[blockIdx.x] = tt;
        __threadfence();
        const unsigned ticket = atomicAdd(&g_cnt, 1u);
        sLast = (ticket == (unsigned)gridDim.x - 1u) ? 1 : 0;
    }
    __syncthreads();

    if (sLast) {
        __threadfence();
        const int nPart = gridDim.x;
        float ssum = 0.f;
        for (int i = tid; i < nPart; i += THREADS) ssum += g_part[i];
        #pragma unroll
        for (int off = 16; off; off >>= 1)
            ssum += __shfl_down_sync(0xffffffffu, ssum, off);
        if (lane == 0) sRed[w] = ssum;
        __syncthreads();
        if (tid == 0) {
            float tt = 0.f;
            #pragma unroll
            for (int i = 0; i < NWARP; ++i) tt += sRed[i];
            const float scale = 2.f / ((float)S * (float)N * (float)D);
            out[(size_t)N * D] = tt * scale;
            g_cnt = 0;                   // reset for next graph replay
        }
    }
}

extern "C" void kernel_launch(void* const* d_in, const int* in_sizes, int n_in,
                              void* d_out, int out_size)
{
    const float* x   = (const float*)d_in[0];
    const float* cbs = (const float*)d_in[1];
    float* out = (float*)d_out;

    const int N = in_sizes[0] / D;              // 262144
    const int S = in_sizes[1] / (C * D);        // 4
    const int nBlocks = N / ROWS;               // 2048

    cudaFuncSetAttribute(rvq_kernel, cudaFuncAttributeMaxDynamicSharedMemorySize,
                         SMEM_BYTES);
    rvq_kernel<<<nBlocks, THREADS, SMEM_BYTES>>>(x, cbs, out, N, S);
}

// round 9
// speedup vs baseline: 1.3956x; 1.1096x over previous
#include <cuda_runtime.h>

// Residual VQ via 3xTF32 tensor-core MMA (mma.sync.m16n8k8, Markidis split).
// x [N,128] fp32, codebooks [S,256,128] fp32.
// Output (float32): x_q [N*128], mean_loss [1], indices [N*S].
//
// One CTA (1024 thr, 32 warps) owns 128 rows across all S stages.
// Warp tile: 32 rows x 32 codes (rt = w&3, ct = w>>2; 8 code tiles x 32 = 256).
// Dots accumulate hi*hi + hi*lo + lo*hi (error ~3e-5, fp32-class), so the only
// rescue tier is the proven fp64 full rescan when top-2 gap < 1e-2.
// x_q = x - final residual. Loss = 2/(S*N*D)*sum(r_new^2), last-CTA reduce.

#define D        128
#define C        256
#define ROWS     128
#define THREADS  1024
#define NWARP    32
#define MAXGRID  4096
#define EPS_GAP  1e-2f
#define LDA      132            // padded row stride (floats)

__device__ float        g_part[MAXGRID];
__device__ unsigned int g_cnt = 0;

// dynamic smem (floats)
#define OFF_A    0
#define OFF_B    (OFF_A + ROWS*LDA)
#define OFF_CN   (OFF_B + C*LDA)
#define OFF_PB1  (OFF_CN + 256)
#define OFF_PB2  (OFF_PB1 + 1024)
#define OFF_PI1  (OFF_PB2 + 1024)
#define OFF_IDX  (OFF_PI1 + 1024)
#define OFF_IALL (OFF_IDX + 128)
#define OFF_RED  (OFF_IALL + 128*8)
#define OFF_CNT  (OFF_RED + 32)
#define OFF_LIST (OFF_CNT + 1)
#define SMEM_FLOATS (OFF_LIST + 128)
#define SMEM_BYTES  (SMEM_FLOATS * 4 + 64)

#define MMA_TF32(c0,c1,c2,c3,a0,a1,a2,a3,b0,b1) \
    asm volatile("mma.sync.aligned.m16n8k8.row.col.f32.tf32.tf32.f32 " \
                 "{%0,%1,%2,%3},{%4,%5,%6,%7},{%8,%9},{%0,%1,%2,%3};" \
                 : "+f"(c0), "+f"(c1), "+f"(c2), "+f"(c3) \
                 : "r"(a0), "r"(a1), "r"(a2), "r"(a3), "r"(b0), "r"(b1))

__device__ __forceinline__ void split_tf32(float x, unsigned& hi, unsigned& lo) {
    asm("cvt.rna.tf32.f32 %0, %1;" : "=r"(hi) : "f"(x));
    const float l = x - __uint_as_float(hi);
    asm("cvt.rna.tf32.f32 %0, %1;" : "=r"(lo) : "f"(l));
}

__global__ void __launch_bounds__(THREADS, 1)
rvq_kernel(const float* __restrict__ x, const float* __restrict__ cbs,
           float* __restrict__ out, int N, int S)
{
    extern __shared__ float sm[];
    float* A       = sm + OFF_A;            // residual [row][k], stride 132
    float* B       = sm + OFF_B;            // codebook [code][k], stride 132
    float* cnorm   = sm + OFF_CN;
    float* pB1     = sm + OFF_PB1;          // partial best  [row*8 + ct]
    float* pB2     = sm + OFF_PB2;          // partial 2nd   [row*8 + ct]
    int*   pI1     = (int*)(sm + OFF_PI1);  // partial index [row*8 + ct]
    int*   sIdx    = (int*)(sm + OFF_IDX);
    float* sIdxAll = sm + OFF_IALL;
    float* sRed    = sm + OFF_RED;
    int*   sCnt    = (int*)(sm + OFF_CNT);
    int*   sList   = (int*)(sm + OFF_LIST);
    __shared__ int sLast;

    const int tid  = threadIdx.x;
    const int lane = tid & 31;
    const int w    = tid >> 5;       // 0..31
    const int g    = lane >> 2;      // mma group (0..7)
    const int t    = lane & 3;       // thread-in-group (0..3)
    const long long rowBase = (long long)blockIdx.x * ROWS;

    const int rt = w & 3;            // row tile: rows [rt*32, rt*32+32)
    const int ct = w >> 2;           // code tile: codes [ct*32, ct*32+32)
    const int arow = rt * 32 + g;

    // ---- load x tile into A: warp w -> rows [4w, 4w+4) ----
    {
        const int r8 = lane >> 3, f = lane & 7;
        const int row = 4 * w + r8;
        #pragma unroll
        for (int j = 0; j < 4; ++j) {
            const int k = j * 32 + f * 4;
            *(float4*)(A + row * LDA + k) =
                *(const float4*)(x + (rowBase + row) * D + k);
        }
    }

    float lsum = 0.f;

    for (int s = 0; s < S; ++s) {
        __syncthreads();             // previous stage done with B
        if (tid == 0) *sCnt = 0;

        // ---- codebook stage s -> B + cnorm (fixed-tree reduce over 8 lanes) ----
        {
            const float* cb = cbs + (size_t)s * C * D;
            const int r8 = lane >> 3, f = lane & 7;
            #pragma unroll
            for (int i = 0; i < 2; ++i) {
                const int code = 8 * w + 4 * i + r8;
                float psum = 0.f;
                #pragma unroll
                for (int j = 0; j < 4; ++j) {
                    const int k = j * 32 + f * 4;
                    const float4 v = *(const float4*)(cb + code * D + k);
                    *(float4*)(B + code * LDA + k) = v;
                    psum += v.x * v.x + v.y * v.y + v.z * v.z + v.w * v.w;
                }
                psum += __shfl_down_sync(0xffffffffu, psum, 4);
                psum += __shfl_down_sync(0xffffffffu, psum, 2);
                psum += __shfl_down_sync(0xffffffffu, psum, 1);
                if (f == 0) cnorm[code] = psum;
            }
        }
        __syncthreads();

        // ---- 3xTF32 MMA: accurate dots[32 rows][32 codes] per warp ----
        // acc[h][n][quad]: h = m-tile (rows arow+16h, +8), n = n-tile (8 codes)
        float acc[2][4][4];
        #pragma unroll
        for (int h = 0; h < 2; ++h)
            #pragma unroll
            for (int n = 0; n < 4; ++n)
                #pragma unroll
                for (int q = 0; q < 4; ++q) acc[h][n][q] = 0.f;

        #pragma unroll 2
        for (int kt = 0; kt < 16; ++kt) {
            const int kb = kt * 8;
            unsigned afh[2][4], afl[2][4];
            #pragma unroll
            for (int h = 0; h < 2; ++h) {
                const int r0 = arow + 16 * h;
                split_tf32(A[ r0      * LDA + kb + t],     afh[h][0], afl[h][0]);
                split_tf32(A[(r0 + 8) * LDA + kb + t],     afh[h][1], afl[h][1]);
                split_tf32(A[ r0      * LDA + kb + t + 4], afh[h][2], afl[h][2]);
                split_tf32(A[(r0 + 8) * LDA + kb + t + 4], afh[h][3], afl[h][3]);
            }
            #pragma unroll
            for (int n = 0; n < 4; ++n) {       // B frags per n-tile (regs reused)
                const int code = ct * 32 + n * 8 + g;
                unsigned bh0, bl0, bh1, bl1;
                split_tf32(B[code * LDA + kb + t],     bh0, bl0);
                split_tf32(B[code * LDA + kb + t + 4], bh1, bl1);
                #pragma unroll
                for (int h = 0; h < 2; ++h) {
                    MMA_TF32(acc[h][n][0], acc[h][n][1], acc[h][n][2], acc[h][n][3],
                             afh[h][0], afh[h][1], afh[h][2], afh[h][3], bh0, bh1);
                    MMA_TF32(acc[h][n][0], acc[h][n][1], acc[h][n][2], acc[h][n][3],
                             afh[h][0], afh[h][1], afh[h][2], afh[h][3], bl0, bl1);
                    MMA_TF32(acc[h][n][0], acc[h][n][1], acc[h][n][2], acc[h][n][3],
                             afl[h][0], afl[h][1], afl[h][2], afl[h][3], bh0, bh1);
                }
            }
        }

        // ---- per-(row, code-tile) top-2 partials ----
        #pragma unroll
        for (int h = 0; h < 2; ++h) {
            #pragma unroll
            for (int rr = 0; rr < 2; ++rr) {        // row = arow + 16h + 8rr
                float b1v = 3.4e38f, b2v = 3.4e38f;
                int   i1  = 0;
                #pragma unroll
                for (int n = 0; n < 4; ++n) {
                    const int code0 = ct * 32 + n * 8 + 2 * t;
                    const float s0 = fmaf(-2.f, acc[h][n][rr * 2 + 0], cnorm[code0]);
                    const float s1 = fmaf(-2.f, acc[h][n][rr * 2 + 1], cnorm[code0 + 1]);
                    if (s0 < b1v) { b2v = b1v; b1v = s0; i1 = code0; }
                    else if (s0 < b2v) b2v = s0;
                    if (s1 < b1v) { b2v = b1v; b1v = s1; i1 = code0 + 1; }
                    else if (s1 < b2v) b2v = s1;
                }
                #pragma unroll
                for (int off = 1; off <= 2; off <<= 1) {
                    const float ov1 = __shfl_xor_sync(0xffffffffu, b1v, off);
                    const int   oi  = __shfl_xor_sync(0xffffffffu, i1, off);
                    const float ov2 = __shfl_xor_sync(0xffffffffu, b2v, off);
                    const float m2  = fminf(fmaxf(b1v, ov1), fminf(b2v, ov2));
                    if (ov1 < b1v || (ov1 == b1v && oi < i1)) { b1v = ov1; i1 = oi; }
                    b2v = m2;
                }
                if (t == 0) {
                    const int row = arow + 16 * h + 8 * rr;
                    pB1[row * 8 + ct] = b1v;
                    pB2[row * 8 + ct] = b2v;
                    pI1[row * 8 + ct] = i1;
                }
            }
        }
        __syncthreads();

        // ---- merge 8 code-tile partials per row; nominate fp64 rescans ----
        if (w < 4) {
            const int row = w * 32 + lane;
            float b1v = 3.4e38f, b2v = 3.4e38f;
            int   i1  = 0;
            #pragma unroll
            for (int c = 0; c < 8; ++c) {
                const float ov1 = pB1[row * 8 + c];
                const float ov2 = pB2[row * 8 + c];
                const int   oi  = pI1[row * 8 + c];
                const float m2  = fminf(fmaxf(b1v, ov1), fminf(b2v, ov2));
                if (ov1 < b1v || (ov1 == b1v && oi < i1)) { b1v = ov1; i1 = oi; }
                b2v = m2;
            }
            if (b2v - b1v < EPS_GAP) {
                const int pos = atomicAdd(sCnt, 1);
                sList[pos] = row;
            } else {
                sIdx[row] = i1;
                sIdxAll[row * 8 + s] = (float)i1;
            }
        }
        __syncthreads();

        // ---- fp64 full rescan for near-tie rows (rare) ----
        {
            const int cnt = *sCnt;
            for (int e = w; e < cnt; e += NWARP) {
                const int row = sList[e];
                double d1 = 1e300; int di = 0x7fffffff;
                #pragma unroll
                for (int cc = 0; cc < 8; ++cc) {
                    const int code = cc * 32 + lane;
                    const float* Bc = B + code * LDA;
                    const float* Arf = A + row * LDA;
                    double dsum = 0.0;
                    for (int k = 0; k < D; ++k) {
                        const double df = (double)Arf[k] - (double)Bc[k];
                        dsum = fma(df, df, dsum);
                    }
                    if (dsum < d1 || (dsum == d1 && code < di)) { d1 = dsum; di = code; }
                }
                #pragma unroll
                for (int off = 16; off; off >>= 1) {
                    const double ov = __shfl_xor_sync(0xffffffffu, d1, off);
                    const int    oi = __shfl_xor_sync(0xffffffffu, di, off);
                    if (ov < d1 || (ov == d1 && oi < di)) { d1 = ov; di = oi; }
                }
                if (lane == 0) {
                    sIdx[row] = di;
                    sIdxAll[row * 8 + s] = (float)di;
                }
            }
        }
        __syncthreads();

        // ---- residual update + loss: warp w -> rows [4w, 4w+4) ----
        {
            const int r8 = lane >> 3, f = lane & 7;
            const int row = 4 * w + r8;
            const int idx = sIdx[row];
            #pragma unroll
            for (int j = 0; j < 4; ++j) {
                const int k = j * 32 + f * 4;
                float4 rv = *(const float4*)(A + row * LDA + k);
                const float4 cv = *(const float4*)(B + idx * LDA + k);
                rv.x -= cv.x; rv.y -= cv.y; rv.z -= cv.z; rv.w -= cv.w;
                *(float4*)(A + row * LDA + k) = rv;
                lsum += rv.x * rv.x + rv.y * rv.y + rv.z * rv.z + rv.w * rv.w;
            }
        }
    }
    __syncthreads();

    // ---- x_q = x - final residual ----
    {
        const int r8 = lane >> 3, f = lane & 7;
        const int row = 4 * w + r8;
        #pragma unroll
        for (int j = 0; j < 4; ++j) {
            const int k = j * 32 + f * 4;
            const float4 xv = *(const float4*)(x + (rowBase + row) * D + k);
            const float4 rv = *(const float4*)(A + row * LDA + k);
            float4 o;
            o.x = xv.x - rv.x; o.y = xv.y - rv.y;
            o.z = xv.z - rv.z; o.w = xv.w - rv.w;
            *(float4*)(out + (rowBase + row) * D + k) = o;
        }
    }

    // ---- indices (float) ----
    float* oIdx = out + (size_t)N * D + 1;
    for (int e = tid; e < ROWS * S; e += THREADS) {
        const int row = e / S, st = e % S;
        oIdx[(rowBase + row) * S + st] = sIdxAll[row * 8 + st];
    }

    // ---- per-CTA loss partial + last-CTA deterministic reduce ----
    #pragma unroll
    for (int off = 16; off; off >>= 1)
        lsum += __shfl_down_sync(0xffffffffu, lsum, off);
    if (lane == 0) sRed[w] = lsum;
    __syncthreads();
    if (tid == 0) {
        float tt = 0.f;
        #pragma unroll
        for (int i = 0; i < NWARP; ++i) tt += sRed[i];
        g_part[blockIdx.x] = tt;
        __threadfence();
        const unsigned ticket = atomicAdd(&g_cnt, 1u);
        sLast = (ticket == (unsigned)gridDim.x - 1u) ? 1 : 0;
    }
    __syncthreads();

    if (sLast) {
        __threadfence();
        const int nPart = gridDim.x;
        float ssum = 0.f;
        for (int i = tid; i < nPart; i += THREADS) ssum += g_part[i];
        #pragma unroll
        for (int off = 16; off; off >>= 1)
            ssum += __shfl_down_sync(0xffffffffu, ssum, off);
        if (lane == 0) sRed[w] = ssum;
        __syncthreads();
        if (tid == 0) {
            float tt = 0.f;
            #pragma unroll
            for (int i = 0; i < NWARP; ++i) tt += sRed[i];
            const float scale = 2.f / ((float)S * (float)N * (float)D);
            out[(size_t)N * D] = tt * scale;
            g_cnt = 0;                   // reset for next graph replay
        }
    }
}

extern "C" void kernel_launch(void* const* d_in, const int* in_sizes, int n_in,
                              void* d_out, int out_size)
{
    const float* x   = (const float*)d_in[0];
    const float* cbs = (const float*)d_in[1];
    float* out = (float*)d_out;

    const int N = in_sizes[0] / D;              // 262144
    const int S = in_sizes[1] / (C * D);        // 4
    const int nBlocks = N / ROWS;               // 2048

    cudaFuncSetAttribute(rvq_kernel, cudaFuncAttributeMaxDynamicSharedMemorySize,
                         SMEM_BYTES);
    rvq_kernel<<<nBlocks, THREADS, SMEM_BYTES>>>(x, cbs, out, N, S);
}

// round 10
// speedup vs baseline: 1.5649x; 1.1213x over previous
#include <cuda_runtime.h>

// Residual VQ via 3xTF32 tensor-core MMA (mma.sync.m16n8k8, Markidis split).
// Split by MASK (hi = x & 0xFFFFE000, exactly tf32; lo = x - hi, exact fp32,
// truncated by the MMA hardware) — no slow CVT chains.
// x [N,128] fp32, codebooks [S,256,128] fp32.
// Output (float32): x_q [N*128], mean_loss [1], indices [N*S].
//
// One CTA (1024 thr, 32 warps) owns 128 rows across all S stages.
// Warp tile: 32 rows x 32 codes (rt = w&3, ct = w>>2; 8 code tiles x 32 = 256).
// Dot error <= ~5e-4 worst case; only rescue tier is the proven fp64 full
// rescan when top-2 gap < 1e-2 (~0.2% of rows).
// x_q = x - final residual. Loss = 2/(S*N*D)*sum(r_new^2), last-CTA reduce.

#define D        128
#define C        256
#define ROWS     128
#define THREADS  1024
#define NWARP    32
#define MAXGRID  4096
#define EPS_GAP  1e-2f
#define LDA      132            // padded row stride (floats)

__device__ float        g_part[MAXGRID];
__device__ unsigned int g_cnt = 0;

// dynamic smem (floats)
#define OFF_A    0
#define OFF_B    (OFF_A + ROWS*LDA)
#define OFF_CN   (OFF_B + C*LDA)
#define OFF_PB1  (OFF_CN + 256)
#define OFF_PB2  (OFF_PB1 + 1024)
#define OFF_PI1  (OFF_PB2 + 1024)
#define OFF_IDX  (OFF_PI1 + 1024)
#define OFF_IALL (OFF_IDX + 128)
#define OFF_RED  (OFF_IALL + 128*8)
#define OFF_CNT  (OFF_RED + 32)
#define OFF_LIST (OFF_CNT + 1)
#define SMEM_FLOATS (OFF_LIST + 128)
#define SMEM_BYTES  (SMEM_FLOATS * 4 + 64)

#define MMA_TF32(c0,c1,c2,c3,a0,a1,a2,a3,b0,b1) \
    asm volatile("mma.sync.aligned.m16n8k8.row.col.f32.tf32.tf32.f32 " \
                 "{%0,%1,%2,%3},{%4,%5,%6,%7},{%8,%9},{%0,%1,%2,%3};" \
                 : "+f"(c0), "+f"(c1), "+f"(c2), "+f"(c3) \
                 : "r"(a0), "r"(a1), "r"(a2), "r"(a3), "r"(b0), "r"(b1))

// hi = x with low 13 mantissa bits cleared (exactly representable in tf32);
// lo = x - hi (exact fp32 subtraction). MMA truncates lo's mantissa in HW.
__device__ __forceinline__ void split_tf32(float x, unsigned& hi, unsigned& lo) {
    hi = __float_as_uint(x) & 0xFFFFE000u;
    lo = __float_as_uint(x - __uint_as_float(hi));
}

__global__ void __launch_bounds__(THREADS, 1)
rvq_kernel(const float* __restrict__ x, const float* __restrict__ cbs,
           float* __restrict__ out, int N, int S)
{
    extern __shared__ float sm[];
    float* A       = sm + OFF_A;            // residual [row][k], stride 132
    float* B       = sm + OFF_B;            // codebook [code][k], stride 132
    float* cnorm   = sm + OFF_CN;
    float* pB1     = sm + OFF_PB1;          // partial best  [row*8 + ct]
    float* pB2     = sm + OFF_PB2;          // partial 2nd   [row*8 + ct]
    int*   pI1     = (int*)(sm + OFF_PI1);  // partial index [row*8 + ct]
    int*   sIdx    = (int*)(sm + OFF_IDX);
    float* sIdxAll = sm + OFF_IALL;
    float* sRed    = sm + OFF_RED;
    int*   sCnt    = (int*)(sm + OFF_CNT);
    int*   sList   = (int*)(sm + OFF_LIST);
    __shared__ int sLast;

    const int tid  = threadIdx.x;
    const int lane = tid & 31;
    const int w    = tid >> 5;       // 0..31
    const int g    = lane >> 2;      // mma group (0..7)
    const int t    = lane & 3;       // thread-in-group (0..3)
    const long long rowBase = (long long)blockIdx.x * ROWS;

    const int rt = w & 3;            // row tile: rows [rt*32, rt*32+32)
    const int ct = w >> 2;           // code tile: codes [ct*32, ct*32+32)
    const int arow = rt * 32 + g;

    // ---- load x tile into A: warp w -> rows [4w, 4w+4) ----
    {
        const int r8 = lane >> 3, f = lane & 7;
        const int row = 4 * w + r8;
        #pragma unroll
        for (int j = 0; j < 4; ++j) {
            const int k = j * 32 + f * 4;
            *(float4*)(A + row * LDA + k) =
                *(const float4*)(x + (rowBase + row) * D + k);
        }
    }

    float lsum = 0.f;

    for (int s = 0; s < S; ++s) {
        __syncthreads();             // previous stage done with B
        if (tid == 0) *sCnt = 0;

        // ---- codebook stage s -> B + cnorm (fixed-tree reduce over 8 lanes) ----
        {
            const float* cb = cbs + (size_t)s * C * D;
            const int r8 = lane >> 3, f = lane & 7;
            #pragma unroll
            for (int i = 0; i < 2; ++i) {
                const int code = 8 * w + 4 * i + r8;
                float psum = 0.f;
                #pragma unroll
                for (int j = 0; j < 4; ++j) {
                    const int k = j * 32 + f * 4;
                    const float4 v = *(const float4*)(cb + code * D + k);
                    *(float4*)(B + code * LDA + k) = v;
                    psum += v.x * v.x + v.y * v.y + v.z * v.z + v.w * v.w;
                }
                psum += __shfl_down_sync(0xffffffffu, psum, 4);
                psum += __shfl_down_sync(0xffffffffu, psum, 2);
                psum += __shfl_down_sync(0xffffffffu, psum, 1);
                if (f == 0) cnorm[code] = psum;
            }
        }
        __syncthreads();

        // ---- 3xTF32 MMA: accurate dots[32 rows][32 codes] per warp ----
        float acc[2][4][4];
        #pragma unroll
        for (int h = 0; h < 2; ++h)
            #pragma unroll
            for (int n = 0; n < 4; ++n)
                #pragma unroll
                for (int q = 0; q < 4; ++q) acc[h][n][q] = 0.f;

        #pragma unroll 2
        for (int kt = 0; kt < 16; ++kt) {
            const int kb = kt * 8;
            unsigned afh[2][4], afl[2][4];
            #pragma unroll
            for (int h = 0; h < 2; ++h) {
                const int r0 = arow + 16 * h;
                split_tf32(A[ r0      * LDA + kb + t],     afh[h][0], afl[h][0]);
                split_tf32(A[(r0 + 8) * LDA + kb + t],     afh[h][1], afl[h][1]);
                split_tf32(A[ r0      * LDA + kb + t + 4], afh[h][2], afl[h][2]);
                split_tf32(A[(r0 + 8) * LDA + kb + t + 4], afh[h][3], afl[h][3]);
            }
            #pragma unroll
            for (int n = 0; n < 4; ++n) {       // B frags per n-tile (regs reused)
                const int code = ct * 32 + n * 8 + g;
                unsigned bh0, bl0, bh1, bl1;
                split_tf32(B[code * LDA + kb + t],     bh0, bl0);
                split_tf32(B[code * LDA + kb + t + 4], bh1, bl1);
                #pragma unroll
                for (int h = 0; h < 2; ++h) {
                    MMA_TF32(acc[h][n][0], acc[h][n][1], acc[h][n][2], acc[h][n][3],
                             afh[h][0], afh[h][1], afh[h][2], afh[h][3], bh0, bh1);
                    MMA_TF32(acc[h][n][0], acc[h][n][1], acc[h][n][2], acc[h][n][3],
                             afh[h][0], afh[h][1], afh[h][2], afh[h][3], bl0, bl1);
                    MMA_TF32(acc[h][n][0], acc[h][n][1], acc[h][n][2], acc[h][n][3],
                             afl[h][0], afl[h][1], afl[h][2], afl[h][3], bh0, bh1);
                }
            }
        }

        // ---- per-(row, code-tile) top-2 partials ----
        #pragma unroll
        for (int h = 0; h < 2; ++h) {
            #pragma unroll
            for (int rr = 0; rr < 2; ++rr) {        // row = arow + 16h + 8rr
                float b1v = 3.4e38f, b2v = 3.4e38f;
                int   i1  = 0;
                #pragma unroll
                for (int n = 0; n < 4; ++n) {
                    const int code0 = ct * 32 + n * 8 + 2 * t;
                    const float s0 = fmaf(-2.f, acc[h][n][rr * 2 + 0], cnorm[code0]);
                    const float s1 = fmaf(-2.f, acc[h][n][rr * 2 + 1], cnorm[code0 + 1]);
                    if (s0 < b1v) { b2v = b1v; b1v = s0; i1 = code0; }
                    else if (s0 < b2v) b2v = s0;
                    if (s1 < b1v) { b2v = b1v; b1v = s1; i1 = code0 + 1; }
                    else if (s1 < b2v) b2v = s1;
                }
                #pragma unroll
                for (int off = 1; off <= 2; off <<= 1) {
                    const float ov1 = __shfl_xor_sync(0xffffffffu, b1v, off);
                    const int   oi  = __shfl_xor_sync(0xffffffffu, i1, off);
                    const float ov2 = __shfl_xor_sync(0xffffffffu, b2v, off);
                    const float m2  = fminf(fmaxf(b1v, ov1), fminf(b2v, ov2));
                    if (ov1 < b1v || (ov1 == b1v && oi < i1)) { b1v = ov1; i1 = oi; }
                    b2v = m2;
                }
                if (t == 0) {
                    const int row = arow + 16 * h + 8 * rr;
                    pB1[row * 8 + ct] = b1v;
                    pB2[row * 8 + ct] = b2v;
                    pI1[row * 8 + ct] = i1;
                }
            }
        }
        __syncthreads();

        // ---- merge 8 code-tile partials per row; nominate fp64 rescans ----
        if (w < 4) {
            const int row = w * 32 + lane;
            float b1v = 3.4e38f, b2v = 3.4e38f;
            int   i1  = 0;
            #pragma unroll
            for (int c = 0; c < 8; ++c) {
                const float ov1 = pB1[row * 8 + c];
                const float ov2 = pB2[row * 8 + c];
                const int   oi  = pI1[row * 8 + c];
                const float m2  = fminf(fmaxf(b1v, ov1), fminf(b2v, ov2));
                if (ov1 < b1v || (ov1 == b1v && oi < i1)) { b1v = ov1; i1 = oi; }
                b2v = m2;
            }
            if (b2v - b1v < EPS_GAP) {
                const int pos = atomicAdd(sCnt, 1);
                sList[pos] = row;
            } else {
                sIdx[row] = i1;
                sIdxAll[row * 8 + s] = (float)i1;
            }
        }
        __syncthreads();

        // ---- fp64 full rescan for near-tie rows (rare) ----
        {
            const int cnt = *sCnt;
            for (int e = w; e < cnt; e += NWARP) {
                const int row = sList[e];
                double d1 = 1e300; int di = 0x7fffffff;
                #pragma unroll
                for (int cc = 0; cc < 8; ++cc) {
                    const int code = cc * 32 + lane;
                    const float* Bc = B + code * LDA;
                    const float* Arf = A + row * LDA;
                    double dsum = 0.0;
                    for (int k = 0; k < D; ++k) {
                        const double df = (double)Arf[k] - (double)Bc[k];
                        dsum = fma(df, df, dsum);
                    }
                    if (dsum < d1 || (dsum == d1 && code < di)) { d1 = dsum; di = code; }
                }
                #pragma unroll
                for (int off = 16; off; off >>= 1) {
                    const double ov = __shfl_xor_sync(0xffffffffu, d1, off);
                    const int    oi = __shfl_xor_sync(0xffffffffu, di, off);
                    if (ov < d1 || (ov == d1 && oi < di)) { d1 = ov; di = oi; }
                }
                if (lane == 0) {
                    sIdx[row] = di;
                    sIdxAll[row * 8 + s] = (float)di;
                }
            }
        }
        __syncthreads();

        // ---- residual update + loss: warp w -> rows [4w, 4w+4) ----
        {
            const int r8 = lane >> 3, f = lane & 7;
            const int row = 4 * w + r8;
            const int idx = sIdx[row];
            #pragma unroll
            for (int j = 0; j < 4; ++j) {
                const int k = j * 32 + f * 4;
                float4 rv = *(const float4*)(A + row * LDA + k);
                const float4 cv = *(const float4*)(B + idx * LDA + k);
                rv.x -= cv.x; rv.y -= cv.y; rv.z -= cv.z; rv.w -= cv.w;
                *(float4*)(A + row * LDA + k) = rv;
                lsum += rv.x * rv.x + rv.y * rv.y + rv.z * rv.z + rv.w * rv.w;
            }
        }
    }
    __syncthreads();

    // ---- x_q = x - final residual ----
    {
        const int r8 = lane >> 3, f = lane & 7;
        const int row = 4 * w + r8;
        #pragma unroll
        for (int j = 0; j < 4; ++j) {
            const int k = j * 32 + f * 4;
            const float4 xv = *(const float4*)(x + (rowBase + row) * D + k);
            const float4 rv = *(const float4*)(A + row * LDA + k);
            float4 o;
            o.x = xv.x - rv.x; o.y = xv.y - rv.y;
            o.z = xv.z - rv.z; o.w = xv.w - rv.w;
            *(float4*)(out + (rowBase + row) * D + k) = o;
        }
    }

    // ---- indices (float) ----
    float* oIdx = out + (size_t)N * D + 1;
    for (int e = tid; e < ROWS * S; e += THREADS) {
        const int row = e / S, st = e % S;
        oIdx[(rowBase + row) * S + st] = sIdxAll[row * 8 + st];
    }

    // ---- per-CTA loss partial + last-CTA deterministic reduce ----
    #pragma unroll
    for (int off = 16; off; off >>= 1)
        lsum += __shfl_down_sync(0xffffffffu, lsum, off);
    if (lane == 0) sRed[w] = lsum;
    __syncthreads();
    if (tid == 0) {
        float tt = 0.f;
        #pragma unroll
        for (int i = 0; i < NWARP; ++i) tt += sRed[i];
        g_part[blockIdx.x] = tt;
        __threadfence();
        const unsigned ticket = atomicAdd(&g_cnt, 1u);
        sLast = (ticket == (unsigned)gridDim.x - 1u) ? 1 : 0;
    }
    __syncthreads();

    if (sLast) {
        __threadfence();
        const int nPart = gridDim.x;
        float ssum = 0.f;
        for (int i = tid; i < nPart; i += THREADS) ssum += g_part[i];
        #pragma unroll
        for (int off = 16; off; off >>= 1)
            ssum += __shfl_down_sync(0xffffffffu, ssum, off);
        if (lane == 0) sRed[w] = ssum;
        __syncthreads();
        if (tid == 0) {
            float tt = 0.f;
            #pragma unroll
            for (int i = 0; i < NWARP; ++i) tt += sRed[i];
            const float scale = 2.f / ((float)S * (float)N * (float)D);
            out[(size_t)N * D] = tt * scale;
            g_cnt = 0;                   // reset for next graph replay
        }
    }
}

extern "C" void kernel_launch(void* const* d_in, const int* in_sizes, int n_in,
                              void* d_out, int out_size)
{
    const float* x   = (const float*)d_in[0];
    const float* cbs = (const float*)d_in[1];
    float* out = (float*)d_out;

    const int N = in_sizes[0] / D;              // 262144
    const int S = in_sizes[1] / (C * D);        // 4
    const int nBlocks = N / ROWS;               // 2048

    cudaFuncSetAttribute(rvq_kernel, cudaFuncAttributeMaxDynamicSharedMemorySize,
                         SMEM_BYTES);
    rvq_kernel<<<nBlocks, THREADS, SMEM_BYTES>>>(x, cbs, out, N, S);
}